// round 3
// baseline (speedup 1.0000x reference)
#include <cuda_runtime.h>

#define CO 256
#define CI 256
#define NW 12

// coef computed once per launch by a tiny kernel (graph-ordered on same stream)
__device__ float g_coef[NW];

__constant__ int c_K[NW] = {3,3,3, 5,5,5, 7,7,7, 9,9,9};
__constant__ int c_D[NW] = {1,3,7, 1,3,7, 1,3,7, 1,3,7};
// left pad (S - (d*(k-1)+1)) / 2 per combo, S = 57
__constant__ int c_P[NW] = {27,25,21, 26,22,14, 25,19,7, 24,16,0};

// softmax(log_softmax(alpha) + gumbels) == softmax(alpha + gumbels)
__global__ void coef_kernel(const float* __restrict__ alpha,
                            const float* __restrict__ gumbels) {
    int t = threadIdx.x;  // one warp
    float v = (t < NW) ? (alpha[t] + gumbels[t]) : -1e30f;
    float m = v;
    #pragma unroll
    for (int o = 16; o > 0; o >>= 1) m = fmaxf(m, __shfl_xor_sync(0xffffffffu, m, o));
    float e = (t < NW) ? __expf(v - m) : 0.0f;
    float s = e;
    #pragma unroll
    for (int o = 16; o > 0; o >>= 1) s += __shfl_xor_sync(0xffffffffu, s, o);
    if (t < NW) g_coef[t] = e / s;
}

// One block per (co,ci) row. Threads 0..11 build acc[0..57) in shared memory;
// then all 256 threads emit one coalesced float4 store each (row length N=1024).
__global__ void __launch_bounds__(256) mcp_kernel(
    const float* __restrict__ w0,  const float* __restrict__ w1,
    const float* __restrict__ w2,  const float* __restrict__ w3,
    const float* __restrict__ w4,  const float* __restrict__ w5,
    const float* __restrict__ w6,  const float* __restrict__ w7,
    const float* __restrict__ w8,  const float* __restrict__ w9,
    const float* __restrict__ w10, const float* __restrict__ w11,
    float* __restrict__ out, int N)
{
    __shared__ float s_acc[64];
    const int row = blockIdx.x;
    const int tid = threadIdx.x;

    if (tid < 64) s_acc[tid] = 0.0f;
    __syncthreads();

    if (tid < NW) {
        const float* wtab[NW] = {w0, w1, w2, w3, w4, w5, w6, w7, w8, w9, w10, w11};
        const float* wp = wtab[tid];
        const int k = c_K[tid];
        const int d = c_D[tid];
        const int p = c_P[tid];
        const float c = g_coef[tid];
        const float* wr = wp + (size_t)row * k;
        for (int j = 0; j < k; ++j)
            atomicAdd(&s_acc[p + j * d], c * wr[j]);
    }
    __syncthreads();

    // pad -> flip -> roll((S+1)//2) composes to:
    //   out[t] = acc[28 - t]      for t in [0, 29)
    //   out[t] = acc[N + 28 - t]  for t in [N-28, N)
    //   out[t] = 0                otherwise
    float4 v = make_float4(0.f, 0.f, 0.f, 0.f);
    const int p0 = tid * 4;
    if (p0 < 29) {
        float a[4];
        #pragma unroll
        for (int e = 0; e < 4; ++e) {
            int q = p0 + e;
            a[e] = (q < 29) ? s_acc[28 - q] : 0.0f;
        }
        v = make_float4(a[0], a[1], a[2], a[3]);
    } else if (p0 + 3 >= N - 28) {
        float a[4];
        #pragma unroll
        for (int e = 0; e < 4; ++e) {
            int q = p0 + e;
            a[e] = (q >= N - 28) ? s_acc[N + 28 - q] : 0.0f;
        }
        v = make_float4(a[0], a[1], a[2], a[3]);
    }
    float4* orow = reinterpret_cast<float4*>(out + (size_t)row * N);
    orow[tid] = v;
}

extern "C" void kernel_launch(void* const* d_in, const int* in_sizes, int n_in,
                              void* d_out, int out_size) {
    const float* w[12];
    for (int i = 0; i < 12; ++i) w[i] = (const float*)d_in[i];
    const float* alpha   = (const float*)d_in[12];
    const float* gumbels = (const float*)d_in[13];
    float* out = (float*)d_out;

    const int rows = CO * CI;                 // 65536
    const int N = out_size / rows;            // input_size (1024)

    coef_kernel<<<1, 32>>>(alpha, gumbels);
    mcp_kernel<<<rows, N / 4>>>(w[0], w[1], w[2], w[3], w[4], w[5],
                                w[6], w[7], w[8], w[9], w[10], w[11],
                                out, N);
}

// round 4
// speedup vs baseline: 5.4037x; 5.4037x over previous
#include <cuda_runtime.h>

#define CO 256
#define CI 256
#define NW 12

__device__ float g_coef[NW];

__constant__ int c_K[NW] = {3,3,3, 5,5,5, 7,7,7, 9,9,9};
__constant__ int c_D[NW] = {1,3,7, 1,3,7, 1,3,7, 1,3,7};
// left pad (S - (d*(k-1)+1)) / 2 per combo, S = 57
__constant__ int c_P[NW] = {27,25,21, 26,22,14, 25,19,7, 24,16,0};

// softmax(log_softmax(alpha) + gumbels) == softmax(alpha + gumbels)
__global__ void coef_kernel(const float* __restrict__ alpha,
                            const float* __restrict__ gumbels) {
    int t = threadIdx.x;  // one warp
    float v = (t < NW) ? (alpha[t] + gumbels[t]) : -1e30f;
    float m = v;
    #pragma unroll
    for (int o = 16; o > 0; o >>= 1) m = fmaxf(m, __shfl_xor_sync(0xffffffffu, m, o));
    float e = (t < NW) ? __expf(v - m) : 0.0f;
    float s = e;
    #pragma unroll
    for (int o = 16; o > 0; o >>= 1) s += __shfl_xor_sync(0xffffffffu, s, o);
    if (t < NW) g_coef[t] = e / s;
}

// One WARP per (co,ci) row — no block-wide barriers.
// Lanes 0..11 accumulate their combo into a per-warp 64-float smem slice,
// then all 32 lanes stream the 1024-float row as 8 independent float4 stores.
__global__ void __launch_bounds__(256) mcp_kernel(
    const float* __restrict__ w0,  const float* __restrict__ w1,
    const float* __restrict__ w2,  const float* __restrict__ w3,
    const float* __restrict__ w4,  const float* __restrict__ w5,
    const float* __restrict__ w6,  const float* __restrict__ w7,
    const float* __restrict__ w8,  const float* __restrict__ w9,
    const float* __restrict__ w10, const float* __restrict__ w11,
    float* __restrict__ out, int N)
{
    __shared__ float s_acc[8][64];
    const int lane = threadIdx.x & 31;
    const int wip  = threadIdx.x >> 5;            // warp index in block
    const int row  = blockIdx.x * 8 + wip;        // one warp per row

    s_acc[wip][lane]      = 0.0f;
    s_acc[wip][lane + 32] = 0.0f;
    __syncwarp();

    if (lane < NW) {
        // uniform code path across lanes; pointer chosen by SEL chain
        const float* wp =
            lane == 0  ? w0  : lane == 1  ? w1  : lane == 2  ? w2  :
            lane == 3  ? w3  : lane == 4  ? w4  : lane == 5  ? w5  :
            lane == 6  ? w6  : lane == 7  ? w7  : lane == 8  ? w8  :
            lane == 9  ? w9  : lane == 10 ? w10 : w11;
        const int k = c_K[lane];
        const int d = c_D[lane];
        const int p = c_P[lane];
        const float c = g_coef[lane];
        const float* wr = wp + (size_t)row * k;

        float wv[9];
        #pragma unroll
        for (int j = 0; j < 9; ++j)
            wv[j] = (j < k) ? wr[j] : 0.0f;       // batched predicated loads (MLP)
        #pragma unroll
        for (int j = 0; j < 9; ++j)
            if (j < k) atomicAdd(&s_acc[wip][p + j * d], c * wv[j]);
    }
    __syncwarp();

    // pad -> flip -> roll((S+1)//2) composes to:
    //   out[t] = acc[28 - t]      for t in [0, 29)
    //   out[t] = acc[N + 28 - t]  for t in [N-28, N)
    //   out[t] = 0                otherwise
    float4* orow = reinterpret_cast<float4*>(out + (size_t)row * N);
    const int iters = N >> 7;                     // 128 floats per warp-iteration
    #pragma unroll 8
    for (int it = 0; it < iters; ++it) {
        const int t0 = it * 128 + lane * 4;
        float4 v = make_float4(0.f, 0.f, 0.f, 0.f);
        if (t0 < 29) {
            float a[4];
            #pragma unroll
            for (int e = 0; e < 4; ++e) {
                int q = t0 + e;
                a[e] = (q < 29) ? s_acc[wip][28 - q] : 0.0f;
            }
            v = make_float4(a[0], a[1], a[2], a[3]);
        } else if (t0 + 3 >= N - 28) {
            float a[4];
            #pragma unroll
            for (int e = 0; e < 4; ++e) {
                int q = t0 + e;
                a[e] = (q >= N - 28) ? s_acc[wip][N + 28 - q] : 0.0f;
            }
            v = make_float4(a[0], a[1], a[2], a[3]);
        }
        orow[t0 >> 2] = v;
    }
}

extern "C" void kernel_launch(void* const* d_in, const int* in_sizes, int n_in,
                              void* d_out, int out_size) {
    const float* w[12];
    for (int i = 0; i < 12; ++i) w[i] = (const float*)d_in[i];
    const float* alpha   = (const float*)d_in[12];
    const float* gumbels = (const float*)d_in[13];
    float* out = (float*)d_out;

    const int rows = CO * CI;                 // 65536
    const int N = out_size / rows;            // input_size (1024)

    coef_kernel<<<1, 32>>>(alpha, gumbels);
    mcp_kernel<<<rows / 8, 256>>>(w[0], w[1], w[2], w[3], w[4], w[5],
                                  w[6], w[7], w[8], w[9], w[10], w[11],
                                  out, N);
}